// round 10
// baseline (speedup 1.0000x reference)
#include <cuda_runtime.h>
#include <stdint.h>

// UniformShardedEmbeddingBags: weights [E,T,D] fp32, indices [B,T,L] int32 -> out [B,T,D] fp32
// E=200000, T=16, D=64, B=4096, L=20
#define EB_E 200000
#define EB_T 16
#define EB_D 64
#define EB_L 20
#define EB_B 4096

// Measured-best family (R7): one warp per bag, each lane owns one float2 slot
// (32 lanes x 8B = two coalesced 128B lines per gathered row), register-resident
// load window, 256-thread blocks, table-major grid (L2 captures the ~1.22x
// per-table row reuse; DRAM bytes are at the dedup floor ~296MB).
//
// R3-R9 established: DRAM-active saturates at ~76% for this random-256B
// pattern regardless of outstanding-load depth (register or cp.async) and
// occupancy. This round consolidates + two micro-levers:
//  1) software-pipelined 10-deep steady window (prologue 10, then
//     consume/issue) - removes the burst-then-drain bubble of v[20] while
//     keeping regs ~32 so occupancy stays ~88%.
//  2) st.global.cs streaming output store - keeps the write-once 16.8MB
//     output from displacing gather lines in L2.
#define WIN 10

__global__ __launch_bounds__(256, 8) void embbag_kernel(
    const float* __restrict__ weights,
    const int* __restrict__ indices,
    float* __restrict__ out)
{
    const int warp = threadIdx.x >> 5;                  // 0..7
    const int lane = threadIdx.x & 31;

    const int t = blockIdx.x >> 9;                      // table 0..15 (512 blocks each)
    const int b = ((blockIdx.x & 511) << 3) + warp;     // batch 0..4095
    const int bag = b * EB_T + t;

    // Lanes 0..19 fetch this bag's indices; one coalesced transaction.
    int myidx = 0;
    if (lane < EB_L) myidx = __ldg(indices + (size_t)bag * EB_L + lane);

    const float2* wbase = reinterpret_cast<const float2*>(weights) + lane;

    // Prologue: fill the 10-deep window.
    float2 v[WIN];
#pragma unroll
    for (int l = 0; l < WIN; ++l) {
        int e = __shfl_sync(0xFFFFFFFFu, myidx, l);
        v[l] = __ldg(wbase + ((size_t)e * EB_T + t) * (EB_D / 2));
    }

    float accx = 0.f, accy = 0.f;

    // Steady state: consume slot l, immediately refill with load l+WIN.
#pragma unroll
    for (int l = 0; l < EB_L - WIN; ++l) {
        accx += v[l % WIN].x;
        accy += v[l % WIN].y;
        int e = __shfl_sync(0xFFFFFFFFu, myidx, l + WIN);
        v[l % WIN] = __ldg(wbase + ((size_t)e * EB_T + t) * (EB_D / 2));
    }

    // Epilogue: drain.
#pragma unroll
    for (int l = EB_L - WIN; l < EB_L; ++l) {
        accx += v[l % WIN].x;
        accy += v[l % WIN].y;
    }

    // Streaming store: write-once output, evict-first in L2.
    float2* dst = reinterpret_cast<float2*>(out) + (size_t)bag * 32 + lane;
    asm volatile("st.global.cs.v2.f32 [%0], {%1, %2};\n"
                 :: "l"(dst), "f"(accx), "f"(accy));
}

extern "C" void kernel_launch(void* const* d_in, const int* in_sizes, int n_in,
                              void* d_out, int out_size)
{
    // weights = 204,800,000 elems ; indices = 1,310,720 elems
    const float* weights = (const float*)d_in[0];
    const int*   indices = (const int*)d_in[1];
    if (n_in >= 2 && in_sizes[0] < in_sizes[1]) {
        weights = (const float*)d_in[1];
        indices = (const int*)d_in[0];
    }
    float* out = (float*)d_out;

    const int block = 256;                 // 8 warps = 8 bags per block
    const int grid = EB_T * 512;           // 8192 blocks, table-major
    embbag_kernel<<<grid, block>>>(weights, indices, out);
}

// round 11
// speedup vs baseline: 1.0012x; 1.0012x over previous
#include <cuda_runtime.h>
#include <stdint.h>

// UniformShardedEmbeddingBags: weights [E,T,D] fp32, indices [B,T,L] int32 -> out [B,T,D] fp32
// E=200000, T=16, D=64, B=4096, L=20
#define EB_E 200000
#define EB_T 16
#define EB_D 64
#define EB_L 20
#define EB_B 4096

// Measured-best structure (R7, 48.9us kernel / 76.4% DRAM-active):
//  - one warp per bag; each lane owns one float2 (8B) slot of the 256B row
//    (32 lanes x 8B = two coalesced 128B lines per gathered row)
//  - PHASE-SPLIT burst: all 20 row loads issued into v[20] before any
//    accumulation (burst-issue beats consume/issue pipelining here: R10
//    showed the steady-state pipeline serializes LDG issue behind returns,
//    dropping DRAM-active to 72.8%)
//  - TABLE-MAJOR grid: per-table working set ~17MB << L2, so the ~1.22x
//    per-table row reuse is captured in L2 (DRAM bytes at dedup floor ~296MB)
//  - plus R9's harmless micro-lever: st.global.cs streaming output store,
//    keeping the write-once 16.8MB output from displacing gather lines in L2.
__global__ __launch_bounds__(256) void embbag_kernel(
    const float* __restrict__ weights,
    const int* __restrict__ indices,
    float* __restrict__ out)
{
    const int warp = threadIdx.x >> 5;                  // 0..7
    const int lane = threadIdx.x & 31;

    const int t = blockIdx.x >> 9;                      // table 0..15 (512 blocks each)
    const int b = ((blockIdx.x & 511) << 3) + warp;     // batch 0..4095
    const int bag = b * EB_T + t;

    // Lanes 0..19 fetch this bag's indices; one coalesced transaction.
    int myidx = 0;
    if (lane < EB_L) myidx = __ldg(indices + (size_t)bag * EB_L + lane);

    const float2* wbase = reinterpret_cast<const float2*>(weights) + lane;

    // Phase 1: issue ALL row loads (no consumer in between).
    float2 v[EB_L];
#pragma unroll
    for (int l = 0; l < EB_L; ++l) {
        int e = __shfl_sync(0xFFFFFFFFu, myidx, l);
        v[l] = __ldg(wbase + ((size_t)e * EB_T + t) * (EB_D / 2));
    }

    // Phase 2: reduce.
    float accx = 0.f, accy = 0.f;
#pragma unroll
    for (int l = 0; l < EB_L; ++l) {
        accx += v[l].x;
        accy += v[l].y;
    }

    // Streaming store: write-once output, evict-first in L2.
    float2* dst = reinterpret_cast<float2*>(out) + (size_t)bag * 32 + lane;
    asm volatile("st.global.cs.v2.f32 [%0], {%1, %2};\n"
                 :: "l"(dst), "f"(accx), "f"(accy));
}

extern "C" void kernel_launch(void* const* d_in, const int* in_sizes, int n_in,
                              void* d_out, int out_size)
{
    // weights = 204,800,000 elems ; indices = 1,310,720 elems
    const float* weights = (const float*)d_in[0];
    const int*   indices = (const int*)d_in[1];
    if (n_in >= 2 && in_sizes[0] < in_sizes[1]) {
        weights = (const float*)d_in[1];
        indices = (const int*)d_in[0];
    }
    float* out = (float*)d_out;

    const int block = 256;                 // 8 warps = 8 bags per block
    const int grid = EB_T * 512;           // 8192 blocks, table-major
    embbag_kernel<<<grid, block>>>(weights, indices, out);
}